// round 7
// baseline (speedup 1.0000x reference)
#include <cuda_runtime.h>
#include <cuda_fp16.h>
#include <cstdint>
#include <math.h>

// Problem constants
#define BB 64
#define PP 196
#define DD 768
#define CC 201
#define KP 5
#define NCLS 200
#define NN (BB*PP)        // 12544
#define JJ (CC*KP)        // 1005
#define JPAD 1024

// Output layout (float32, concatenated in reference return order)
#define OFF_LOGITS 0
#define SZ_LOGITS  (NN*JJ)
#define OFF_IMG    (OFF_LOGITS + SZ_LOGITS)
#define SZ_IMG     (BB*JJ)
#define OFF_CLS    (OFF_IMG + SZ_IMG)
#define SZ_CLS     (BB*NCLS)
#define OFF_ASGN   (OFF_CLS + SZ_CLS)
#define SZ_ASGN    (NN)
#define OFF_PNEW   (OFF_ASGN + SZ_ASGN)
#define SZ_PNEW    (CC*KP*DD)

// Device scratch
__device__ __align__(16) __half g_pth[NN*DD];     // fp16(A)
__device__ __align__(16) __half g_pt2[NN*DD];     // fp16(Ah + 64*(A-Ah))
__device__ __align__(16) __half g_pnh[JPAD*DD];   // fp16(B)
__device__ __align__(16) __half g_pn2[JPAD*DD];   // fp16(Bh + 64*(B-Bh))
__device__ float g_inv[NN];                       // 1/||rpt_row||
__device__ float g_sw[NCLS*KP];

// ---------------------------------------------------------------------------
// PTX helpers
// ---------------------------------------------------------------------------
__device__ __forceinline__ void ldsm_x4(uint32_t* r, uint32_t addr) {
    asm volatile("ldmatrix.sync.aligned.m8n8.x4.shared.b16 {%0,%1,%2,%3}, [%4];"
                 : "=r"(r[0]), "=r"(r[1]), "=r"(r[2]), "=r"(r[3]) : "r"(addr));
}
__device__ __forceinline__ void mma_fp16(float* d, const uint32_t* a, const uint32_t* b) {
    asm volatile(
        "mma.sync.aligned.m16n8k16.row.col.f32.f16.f16.f32 "
        "{%0,%1,%2,%3}, {%4,%5,%6,%7}, {%8,%9}, {%0,%1,%2,%3};"
        : "+f"(d[0]), "+f"(d[1]), "+f"(d[2]), "+f"(d[3])
        : "r"(a[0]), "r"(a[1]), "r"(a[2]), "r"(a[3]), "r"(b[0]), "r"(b[1]));
}
__device__ __forceinline__ void cpa16(uint32_t smem, const void* g) {
    asm volatile("cp.async.ca.shared.global [%0], [%1], 16;" :: "r"(smem), "l"(g));
}
__device__ __forceinline__ void cpa_commit() {
    asm volatile("cp.async.commit_group;" ::: "memory");
}
template <int N>
__device__ __forceinline__ void cpa_wait() {
    asm volatile("cp.async.wait_group %0;" :: "n"(N) : "memory");
}

// ---------------------------------------------------------------------------
// Row L2 normalization + fp16 Ootomo split (warp per row)
// ---------------------------------------------------------------------------
__global__ __launch_bounds__(256) void norm_kernel(const float* __restrict__ pt,
                            const float* __restrict__ rpt,
                            const float* __restrict__ proto) {
    const int r = blockIdx.x * 8 + (threadIdx.x >> 5);
    const int lane = threadIdx.x & 31;
    if (r >= 2*NN + JPAD) return;

    if (r < NN) {
        const float* src = pt + (size_t)r*DD;
        float s = 0.0f;
        for (int i = lane; i < DD; i += 32) { float v = src[i]; s += v*v; }
        #pragma unroll
        for (int o = 16; o > 0; o >>= 1) s += __shfl_xor_sync(0xffffffffu, s, o);
        float inv = 1.0f / fmaxf(sqrtf(s), 1e-12f);
        for (int i = lane; i < DD; i += 32) {
            float x = src[i] * inv;
            __half h = __float2half(x);
            float hf = __half2float(h);
            g_pth[(size_t)r*DD + i] = h;
            g_pt2[(size_t)r*DD + i] = __float2half(fmaf(64.0f, x - hf, hf));
        }
    } else if (r < 2*NN) {
        int rr = r - NN;
        const float* src = rpt + (size_t)rr*DD;
        float s = 0.0f;
        for (int i = lane; i < DD; i += 32) { float v = src[i]; s += v*v; }
        #pragma unroll
        for (int o = 16; o > 0; o >>= 1) s += __shfl_xor_sync(0xffffffffu, s, o);
        if (lane == 0) g_inv[rr] = 1.0f / fmaxf(sqrtf(s), 1e-12f);
    } else {
        int j = r - 2*NN;
        if (j >= JJ) {
            __half z = __float2half(0.0f);
            for (int i = lane; i < DD; i += 32) {
                g_pnh[(size_t)j*DD + i] = z;
                g_pn2[(size_t)j*DD + i] = z;
            }
            return;
        }
        const float* src = proto + (size_t)j*DD;
        float s = 0.0f;
        for (int i = lane; i < DD; i += 32) { float v = src[i]; s += v*v; }
        #pragma unroll
        for (int o = 16; o > 0; o >>= 1) s += __shfl_xor_sync(0xffffffffu, s, o);
        float inv = 1.0f / fmaxf(sqrtf(s), 1e-12f);
        for (int i = lane; i < DD; i += 32) {
            float x = src[i] * inv;
            __half h = __float2half(x);
            float hf = __half2float(h);
            g_pnh[(size_t)j*DD + i] = h;
            g_pn2[(size_t)j*DD + i] = __float2half(fmaf(64.0f, x - hf, hf));
        }
    }
}

// ---------------------------------------------------------------------------
// sw = softmax(sa_weights, axis=-1) * K
// ---------------------------------------------------------------------------
__global__ void sw_kernel(const float* __restrict__ sa) {
    int c = blockIdx.x * blockDim.x + threadIdx.x;
    if (c >= NCLS) return;
    float w[KP];
    float m = -1e30f;
    for (int k = 0; k < KP; k++) { w[k] = sa[c*KP+k]; m = fmaxf(m, w[k]); }
    float s = 0.0f;
    for (int k = 0; k < KP; k++) { w[k] = expf(w[k]-m); s += w[k]; }
    for (int k = 0; k < KP; k++) g_sw[c*KP+k] = w[k] / s * 5.0f;
}

// ---------------------------------------------------------------------------
// 2-product fp16 GEMM (Ootomo):  out = P0 + (P1 - P0)/64
// CTA 128x128, BK=32, 8 warps (4M x 2N), warp tile 32x64, 3-stage cp.async
// 1 CTA/SM (128 accum regs/thread)
// ---------------------------------------------------------------------------
#define SAS 40                               // smem row stride (fp16 elems)
#define A_TB (128*SAS*2)                     // 10240 bytes per array (128 rows)
#define STAGE_B (4*A_TB)                     // Ah, A2, Bh, B2 -> 40960 per stage
#define NSTAGE 3
#define SMEM_GEMM (NSTAGE*STAGE_B)           // 122880
#define NCHUNK (DD/32)                       // 24

__global__ __launch_bounds__(256, 1) void gemm_mma_kernel(float* __restrict__ out) {
    extern __shared__ __align__(16) char smem[];
    const uint32_t sb = (uint32_t)__cvta_generic_to_shared(smem);

    const int tid  = threadIdx.x;
    const int lane = tid & 31;
    const int wid  = tid >> 5;
    const int wm   = wid & 3;      // M 32-block
    const int wn   = wid >> 2;     // N 64-block
    const int bm   = blockIdx.x * 128;
    const int bn   = blockIdx.y * 128;

    const int arow = (lane & 7) + ((lane >> 3) & 1) * 8;
    const int acol = (lane >> 4) * 8;
    const int brow = (lane & 7) + ((lane >> 4) & 1) * 8;
    const int bcol = ((lane >> 3) & 1) * 8;

    float acc0[2][8][4], acc1[2][8][4];
    #pragma unroll
    for (int i = 0; i < 2; i++)
        #pragma unroll
        for (int j = 0; j < 8; j++)
            #pragma unroll
            for (int q = 0; q < 4; q++) { acc0[i][j][q] = 0.0f; acc1[i][j][q] = 0.0f; }

    const int gr0 = tid >> 2;          // 0..63
    const int gq0 = tid & 3;           // 16B chunk

    auto load_chunk = [&](int kt, int s) {
        uint32_t st = sb + s*STAGE_B;
        #pragma unroll
        for (int l = 0; l < 2; l++) {
            int row = gr0 + l*64;
            uint32_t so = (uint32_t)(row*SAS + gq0*8) * 2;
            size_t gi = (size_t)(bm + row)*DD + kt + gq0*8;
            size_t gj = (size_t)(bn + row)*DD + kt + gq0*8;
            cpa16(st + so,          g_pth + gi);
            cpa16(st + A_TB + so,   g_pt2 + gi);
            cpa16(st + 2*A_TB + so, g_pnh + gj);
            cpa16(st + 3*A_TB + so, g_pn2 + gj);
        }
        cpa_commit();
    };

    load_chunk(0, 0);
    load_chunk(32, 1);

    for (int i = 0; i < NCHUNK; i++) {
        const int s = i % NSTAGE;
        if (i + 2 < NCHUNK) {
            load_chunk((i+2)*32, (i+2) % NSTAGE);
            cpa_wait<2>();
        } else if (i + 1 < NCHUNK) {
            cpa_wait<1>();
        } else {
            cpa_wait<0>();
        }
        __syncthreads();

        const uint32_t aAh = sb + s*STAGE_B;
        const uint32_t aA2 = aAh + A_TB;
        const uint32_t aBh = aAh + 2*A_TB;
        const uint32_t aB2 = aAh + 3*A_TB;

        #pragma unroll
        for (int ks = 0; ks < 32; ks += 16) {
            uint32_t ah[2][4], a2[2][4];
            #pragma unroll
            for (int mi = 0; mi < 2; mi++) {
                uint32_t off = (uint32_t)((wm*32 + mi*16 + arow)*SAS + ks + acol) * 2;
                ldsm_x4(ah[mi], aAh + off);
                ldsm_x4(a2[mi], aA2 + off);
            }
            #pragma unroll
            for (int nb = 0; nb < 4; nb++) {
                uint32_t bh[4], b2[4];
                uint32_t off = (uint32_t)((wn*64 + nb*16 + brow)*SAS + ks + bcol) * 2;
                ldsm_x4(bh, aBh + off);
                ldsm_x4(b2, aB2 + off);
                #pragma unroll
                for (int mi = 0; mi < 2; mi++) {
                    mma_fp16(acc0[mi][nb*2+0], ah[mi], bh+0);
                    mma_fp16(acc0[mi][nb*2+1], ah[mi], bh+2);
                    mma_fp16(acc1[mi][nb*2+0], a2[mi], b2+0);
                    mma_fp16(acc1[mi][nb*2+1], a2[mi], b2+2);
                }
            }
        }
        __syncthreads();
    }

    // epilogue: combine P0 + (P1-P0)/64, scalar fp32 stores (JJ odd)
    #pragma unroll
    for (int mi = 0; mi < 2; mi++) {
        #pragma unroll
        for (int nf = 0; nf < 8; nf++) {
            int col = bn + wn*64 + nf*8 + (lane & 3)*2;
            #pragma unroll
            for (int h = 0; h < 2; h++) {
                int row = bm + wm*32 + mi*16 + (lane >> 2) + h*8;
                size_t base = (size_t)row*JJ + col;
                float p0a = acc0[mi][nf][h*2+0], p1a = acc1[mi][nf][h*2+0];
                float p0b = acc0[mi][nf][h*2+1], p1b = acc1[mi][nf][h*2+1];
                float va = p0a + (p1a - p0a) * 0.015625f;
                float vb = p0b + (p1b - p0b) * 0.015625f;
                if (col < JJ)     out[base]     = va;
                if (col + 1 < JJ) out[base + 1] = vb;
            }
        }
    }
}

// ---------------------------------------------------------------------------
// image_logits[b, j] = max_p logits[b, p, j]
// ---------------------------------------------------------------------------
__global__ void imgmax_kernel(const float* __restrict__ logits, float* __restrict__ img) {
    int t = blockIdx.x * blockDim.x + threadIdx.x;
    if (t >= BB*JJ) return;
    int b = t / JJ, j = t % JJ;
    const float* p = logits + (size_t)b*PP*JJ + j;
    float m = -1e30f;
    #pragma unroll 4
    for (int i = 0; i < PP; i++) m = fmaxf(m, p[(size_t)i*JJ]);
    img[(size_t)b*JJ + j] = m;
}

// ---------------------------------------------------------------------------
// class_logits[b, c] = sum_k img[b, c, k]*sw[c, k] / TEMP
// ---------------------------------------------------------------------------
__global__ void cls_kernel(const float* __restrict__ img, float* __restrict__ cls) {
    int t = blockIdx.x * blockDim.x + threadIdx.x;
    if (t >= BB*NCLS) return;
    int b = t / NCLS, c = t % NCLS;
    float s = 0.0f;
    #pragma unroll
    for (int k = 0; k < KP; k++) s += img[(size_t)b*JJ + c*KP + k] * g_sw[c*KP+k];
    cls[t] = s / 0.2f;
}

// ---------------------------------------------------------------------------
// Per-class: deterministic compaction + Sinkhorn + assignment + P_new
// ---------------------------------------------------------------------------
#define MAXN 1024
__global__ __launch_bounds__(256) void sinkhorn_kernel(
        const float* __restrict__ logits, const int* __restrict__ labels,
        const float* __restrict__ proto, const float* __restrict__ rpt,
        float* __restrict__ assign, float* __restrict__ pnew) {
    const int c = blockIdx.x;
    const int tid = threadIdx.x;
    const int lane = tid & 31, w = tid >> 5;

    __shared__ int   s_idx[MAXN];
    __shared__ float Q[KP][MAXN];
    __shared__ float red[256];
    __shared__ int   warp_cnt[8], warp_off[8];
    __shared__ int   s_n;

    if (tid == 0) s_n = 0;
    __syncthreads();

    for (int base = 0; base < NN; base += 256) {
        int n = base + tid;
        bool p = (labels[n] == c);
        unsigned bal = __ballot_sync(0xffffffffu, p);
        if (lane == 0) warp_cnt[w] = __popc(bal);
        __syncthreads();
        if (tid == 0) {
            int s = s_n;
            #pragma unroll
            for (int i = 0; i < 8; i++) { warp_off[i] = s; s += warp_cnt[i]; }
            s_n = s;
        }
        __syncthreads();
        if (p) {
            int pos = warp_off[w] + __popc(bal & ((1u << lane) - 1u));
            if (pos < MAXN) s_idx[pos] = n;
        }
        __syncthreads();
    }
    const int Nc = min(s_n, MAXN);

    if (Nc == 0) {
        for (int x = tid; x < KP*DD; x += 256)
            pnew[(size_t)c*KP*DD + x] = proto[(size_t)c*KP*DD + x];
        return;
    }

    for (int i = tid; i < Nc; i += 256) {
        const float* lp = logits + (size_t)s_idx[i]*JJ + c*KP;
        #pragma unroll
        for (int k = 0; k < KP; k++) Q[k][i] = expf(lp[k] * 20.0f);
    }
    __syncthreads();

    float s = 0.0f;
    for (int k = 0; k < KP; k++)
        for (int i = tid; i < Nc; i += 256) s += Q[k][i];
    red[tid] = s; __syncthreads();
    for (int o = 128; o > 0; o >>= 1) { if (tid < o) red[tid] += red[tid+o]; __syncthreads(); }
    float tot = red[0];
    __syncthreads();
    float dTot = (tot > 0.0f) ? tot : 1.0f;
    for (int k = 0; k < KP; k++)
        for (int i = tid; i < Nc; i += 256) Q[k][i] /= dTot;
    __syncthreads();

    const float fNc = (float)Nc;
    for (int it = 0; it < 3; it++) {
        for (int k = 0; k < KP; k++) {
            float rs = 0.0f;
            for (int i = tid; i < Nc; i += 256) rs += Q[k][i];
            red[tid] = rs; __syncthreads();
            for (int o = 128; o > 0; o >>= 1) { if (tid < o) red[tid] += red[tid+o]; __syncthreads(); }
            float r = red[0];
            __syncthreads();
            float dr = (r > 0.0f) ? r : 1.0f;
            for (int i = tid; i < Nc; i += 256) Q[k][i] = Q[k][i] / dr / 5.0f;
            __syncthreads();
        }
        for (int i = tid; i < Nc; i += 256) {
            float cs = Q[0][i]+Q[1][i]+Q[2][i]+Q[3][i]+Q[4][i];
            float dc = (cs > 0.0f) ? cs : 1.0f;
            #pragma unroll
            for (int k = 0; k < KP; k++) Q[k][i] = Q[k][i] / dc / fNc;
        }
        __syncthreads();
    }
    for (int k = 0; k < KP; k++)
        for (int i = tid; i < Nc; i += 256) Q[k][i] *= fNc;
    __syncthreads();

    for (int i = tid; i < Nc; i += 256) {
        float best = Q[0][i]; int ba = 0;
        #pragma unroll
        for (int k = 1; k < KP; k++) if (Q[k][i] > best) { best = Q[k][i]; ba = k; }
        assign[s_idx[i]] = (float)(c*KP + ba);
    }
    __syncthreads();

    // fold row inverse-norm into Q (patches_flat = rpt_row * inv)
    for (int i = tid; i < Nc; i += 256) {
        float inv = g_inv[s_idx[i]];
        #pragma unroll
        for (int k = 0; k < KP; k++) Q[k][i] *= inv;
    }
    __syncthreads();

    const int d0 = tid * 3;
    float acc[KP][3];
    #pragma unroll
    for (int k = 0; k < KP; k++) { acc[k][0]=0.f; acc[k][1]=0.f; acc[k][2]=0.f; }
    for (int i = 0; i < Nc; i++) {
        const float* xp = rpt + (size_t)s_idx[i]*DD + d0;
        float x0 = xp[0], x1 = xp[1], x2 = xp[2];
        #pragma unroll
        for (int k = 0; k < KP; k++) {
            float q = Q[k][i];
            acc[k][0] = fmaf(q, x0, acc[k][0]);
            acc[k][1] = fmaf(q, x1, acc[k][1]);
            acc[k][2] = fmaf(q, x2, acc[k][2]);
        }
    }
    const float g = 0.999f, og = 1.0f - 0.999f;
    #pragma unroll
    for (int k = 0; k < KP; k++) {
        size_t basep = ((size_t)c*KP + k)*DD + d0;
        #pragma unroll
        for (int j = 0; j < 3; j++)
            pnew[basep + j] = g * proto[basep + j] + og * acc[k][j];
    }
}

// ---------------------------------------------------------------------------
extern "C" void kernel_launch(void* const* d_in, const int* in_sizes, int n_in,
                              void* d_out, int out_size) {
    const float* pt    = (const float*)d_in[0];
    const float* rpt   = (const float*)d_in[1];
    const float* proto = (const float*)d_in[2];
    const float* sa    = (const float*)d_in[3];
    const int*   lbl   = (const int*)  d_in[4];
    float* out = (float*)d_out;

    cudaFuncSetAttribute(gemm_mma_kernel,
                         cudaFuncAttributeMaxDynamicSharedMemorySize, SMEM_GEMM);

    norm_kernel<<<(2*NN + JPAD + 7)/8, 256>>>(pt, rpt, proto);
    sw_kernel<<<1, 256>>>(sa);
    {
        dim3 grid(NN/128, JPAD/128);   // 98 x 8
        gemm_mma_kernel<<<grid, 256, SMEM_GEMM>>>(out + OFF_LOGITS);
    }
    imgmax_kernel<<<(BB*JJ + 255)/256, 256>>>(out + OFF_LOGITS, out + OFF_IMG);
    cls_kernel<<<(BB*NCLS + 255)/256, 256>>>(out + OFF_IMG, out + OFF_CLS);
    sinkhorn_kernel<<<CC, 256>>>(out + OFF_LOGITS, lbl, proto, rpt,
                                 out + OFF_ASGN, out + OFF_PNEW);
}

// round 8
// speedup vs baseline: 1.1115x; 1.1115x over previous
#include <cuda_runtime.h>
#include <cuda_fp16.h>
#include <cstdint>
#include <math.h>

// Problem constants
#define BB 64
#define PP 196
#define DD 768
#define CC 201
#define KP 5
#define NCLS 200
#define NN (BB*PP)        // 12544
#define JJ (CC*KP)        // 1005
#define JPAD 1024

// Output layout
#define OFF_LOGITS 0
#define SZ_LOGITS  (NN*JJ)
#define OFF_IMG    (OFF_LOGITS + SZ_LOGITS)
#define SZ_IMG     (BB*JJ)
#define OFF_CLS    (OFF_IMG + SZ_IMG)
#define SZ_CLS     (BB*NCLS)
#define OFF_ASGN   (OFF_CLS + SZ_CLS)
#define SZ_ASGN    (NN)
#define OFF_PNEW   (OFF_ASGN + SZ_ASGN)
#define SZ_PNEW    (CC*KP*DD)

// Device scratch
__device__ __align__(16) __half g_pth[NN*DD];     // fp16(A)
__device__ __align__(16) __half g_pt2[NN*DD];     // fp16(Ah + 64*(A-Ah))
__device__ __align__(16) __half g_pnh[JPAD*DD];   // fp16(B)
__device__ __align__(16) __half g_pn2[JPAD*DD];   // fp16(Bh + 64*(B-Bh))
__device__ float g_inv[NN];                       // 1/||rpt_row||
__device__ float g_sw[NCLS*KP];

// ---------------------------------------------------------------------------
// PTX helpers
// ---------------------------------------------------------------------------
__device__ __forceinline__ void ldsm_x4(uint32_t* r, uint32_t addr) {
    asm volatile("ldmatrix.sync.aligned.m8n8.x4.shared.b16 {%0,%1,%2,%3}, [%4];"
                 : "=r"(r[0]), "=r"(r[1]), "=r"(r[2]), "=r"(r[3]) : "r"(addr));
}
__device__ __forceinline__ void mma_fp16(float* d, const uint32_t* a, const uint32_t* b) {
    asm volatile(
        "mma.sync.aligned.m16n8k16.row.col.f32.f16.f16.f32 "
        "{%0,%1,%2,%3}, {%4,%5,%6,%7}, {%8,%9}, {%0,%1,%2,%3};"
        : "+f"(d[0]), "+f"(d[1]), "+f"(d[2]), "+f"(d[3])
        : "r"(a[0]), "r"(a[1]), "r"(a[2]), "r"(a[3]), "r"(b[0]), "r"(b[1]));
}
__device__ __forceinline__ void cpa16(uint32_t smem, const void* g) {
    asm volatile("cp.async.ca.shared.global [%0], [%1], 16;" :: "r"(smem), "l"(g));
}
__device__ __forceinline__ void cpa_commit() {
    asm volatile("cp.async.commit_group;" ::: "memory");
}
template <int N>
__device__ __forceinline__ void cpa_wait() {
    asm volatile("cp.async.wait_group %0;" :: "n"(N) : "memory");
}

// ---------------------------------------------------------------------------
// Row L2 normalization + fp16 Ootomo split (warp per row)
// ---------------------------------------------------------------------------
__global__ __launch_bounds__(256) void norm_kernel(const float* __restrict__ pt,
                            const float* __restrict__ rpt,
                            const float* __restrict__ proto) {
    const int r = blockIdx.x * 8 + (threadIdx.x >> 5);
    const int lane = threadIdx.x & 31;
    if (r >= 2*NN + JPAD) return;

    if (r < NN) {
        const float* src = pt + (size_t)r*DD;
        float s = 0.0f;
        for (int i = lane; i < DD; i += 32) { float v = src[i]; s += v*v; }
        #pragma unroll
        for (int o = 16; o > 0; o >>= 1) s += __shfl_xor_sync(0xffffffffu, s, o);
        float inv = 1.0f / fmaxf(sqrtf(s), 1e-12f);
        for (int i = lane; i < DD; i += 32) {
            float x = src[i] * inv;
            __half h = __float2half(x);
            float hf = __half2float(h);
            g_pth[(size_t)r*DD + i] = h;
            g_pt2[(size_t)r*DD + i] = __float2half(fmaf(64.0f, x - hf, hf));
        }
    } else if (r < 2*NN) {
        int rr = r - NN;
        const float* src = rpt + (size_t)rr*DD;
        float s = 0.0f;
        for (int i = lane; i < DD; i += 32) { float v = src[i]; s += v*v; }
        #pragma unroll
        for (int o = 16; o > 0; o >>= 1) s += __shfl_xor_sync(0xffffffffu, s, o);
        if (lane == 0) g_inv[rr] = 1.0f / fmaxf(sqrtf(s), 1e-12f);
    } else {
        int j = r - 2*NN;
        if (j >= JJ) {
            __half z = __float2half(0.0f);
            for (int i = lane; i < DD; i += 32) {
                g_pnh[(size_t)j*DD + i] = z;
                g_pn2[(size_t)j*DD + i] = z;
            }
            return;
        }
        const float* src = proto + (size_t)j*DD;
        float s = 0.0f;
        for (int i = lane; i < DD; i += 32) { float v = src[i]; s += v*v; }
        #pragma unroll
        for (int o = 16; o > 0; o >>= 1) s += __shfl_xor_sync(0xffffffffu, s, o);
        float inv = 1.0f / fmaxf(sqrtf(s), 1e-12f);
        for (int i = lane; i < DD; i += 32) {
            float x = src[i] * inv;
            __half h = __float2half(x);
            float hf = __half2float(h);
            g_pnh[(size_t)j*DD + i] = h;
            g_pn2[(size_t)j*DD + i] = __float2half(fmaf(64.0f, x - hf, hf));
        }
    }
}

// ---------------------------------------------------------------------------
// sw = softmax(sa_weights, axis=-1) * K
// ---------------------------------------------------------------------------
__global__ void sw_kernel(const float* __restrict__ sa) {
    int c = blockIdx.x * blockDim.x + threadIdx.x;
    if (c >= NCLS) return;
    float w[KP];
    float m = -1e30f;
    for (int k = 0; k < KP; k++) { w[k] = sa[c*KP+k]; m = fmaxf(m, w[k]); }
    float s = 0.0f;
    for (int k = 0; k < KP; k++) { w[k] = expf(w[k]-m); s += w[k]; }
    for (int k = 0; k < KP; k++) g_sw[c*KP+k] = w[k] / s * 5.0f;
}

// ---------------------------------------------------------------------------
// 2-product fp16 GEMM (Ootomo, product-split warps):  out = P0 + (P1-P0)/64
// Persistent: grid=148, each CTA loops over 784 tiles of 128x128.
// 512 threads = 16 warps: tile (wid&7) = 4Mx2N of 32x64; product = wid>>3.
// 2-stage cp.async, BK=32.
// ---------------------------------------------------------------------------
#define SAS 40                               // smem row stride (fp16 elems)
#define A_TB (128*SAS*2)                     // 10240 bytes per array (128 rows)
#define STAGE_B (4*A_TB)                     // Ah, A2, Bh, B2 -> 40960 per stage
#define SMEM_GEMM (2*STAGE_B)                // 81920
#define NCHUNK (DD/32)                       // 24
#define MTILES (NN/128)                      // 98
#define NTILES (JPAD/128)                    // 8
#define TOTTILES (MTILES*NTILES)             // 784

__global__ __launch_bounds__(512, 1) void gemm_mma_kernel(float* __restrict__ out) {
    extern __shared__ __align__(16) char smem[];
    const uint32_t sb = (uint32_t)__cvta_generic_to_shared(smem);

    const int tid  = threadIdx.x;
    const int lane = tid & 31;
    const int wid  = tid >> 5;
    const int p    = wid >> 3;     // product: 0 -> (Ah,Bh), 1 -> (A2,B2)
    const int t    = wid & 7;      // output tile within CTA
    const int wm   = t & 3;        // M 32-block
    const int wn   = t >> 2;       // N 64-block

    const int arow = (lane & 7) + ((lane >> 3) & 1) * 8;
    const int acol = (lane >> 4) * 8;
    const int brow = (lane & 7) + ((lane >> 4) & 1) * 8;
    const int bcol = ((lane >> 3) & 1) * 8;

    // this warp's array base offsets within a stage
    const uint32_t offA = (uint32_t)p * A_TB;          // Ah or A2
    const uint32_t offB = (uint32_t)(2 + p) * A_TB;    // Bh or B2

    for (int tile = blockIdx.x; tile < TOTTILES; tile += gridDim.x) {
        const int bm = (tile / NTILES) * 128;
        const int bn = (tile % NTILES) * 128;

        float acc[2][8][4];
        #pragma unroll
        for (int i = 0; i < 2; i++)
            #pragma unroll
            for (int j = 0; j < 8; j++)
                #pragma unroll
                for (int q = 0; q < 4; q++) acc[i][j][q] = 0.0f;

        // loader: 2048 16B-chunks per stage fill, 4 per thread
        auto load_chunk = [&](int kt, int s) {
            uint32_t st = sb + s*STAGE_B;
            #pragma unroll
            for (int i = 0; i < 4; i++) {
                int u = tid + i*512;
                int arr = u >> 9;            // 0..3
                int within = u & 511;
                int row = within >> 2;
                int q = within & 3;
                uint32_t so = st + arr*A_TB + (uint32_t)(row*SAS + q*8)*2;
                const __half* srcs;
                size_t gi;
                if (arr == 0)      { srcs = g_pth; gi = (size_t)(bm+row)*DD; }
                else if (arr == 1) { srcs = g_pt2; gi = (size_t)(bm+row)*DD; }
                else if (arr == 2) { srcs = g_pnh; gi = (size_t)(bn+row)*DD; }
                else               { srcs = g_pn2; gi = (size_t)(bn+row)*DD; }
                cpa16(so, srcs + gi + kt + q*8);
            }
            cpa_commit();
        };

        load_chunk(0, 0);

        for (int i = 0; i < NCHUNK; i++) {
            const int s = i & 1;
            if (i + 1 < NCHUNK) {
                load_chunk((i+1)*32, (i+1) & 1);
                cpa_wait<1>();
            } else {
                cpa_wait<0>();
            }
            __syncthreads();

            const uint32_t aA = sb + s*STAGE_B + offA;
            const uint32_t aB = sb + s*STAGE_B + offB;

            #pragma unroll
            for (int ks = 0; ks < 32; ks += 16) {
                uint32_t af[2][4];
                #pragma unroll
                for (int mi = 0; mi < 2; mi++) {
                    uint32_t off = (uint32_t)((wm*32 + mi*16 + arow)*SAS + ks + acol) * 2;
                    ldsm_x4(af[mi], aA + off);
                }
                #pragma unroll
                for (int nb = 0; nb < 4; nb++) {
                    uint32_t bf[4];
                    uint32_t off = (uint32_t)((wn*64 + nb*16 + brow)*SAS + ks + bcol) * 2;
                    ldsm_x4(bf, aB + off);
                    #pragma unroll
                    for (int mi = 0; mi < 2; mi++) {
                        mma_fp16(acc[mi][nb*2+0], af[mi], bf+0);
                        mma_fp16(acc[mi][nb*2+1], af[mi], bf+2);
                    }
                }
            }
            __syncthreads();
        }

        // epilogue: P1 warps stage to smem; P0 warps combine + store
        float* xbuf = (float*)smem;     // 8 tiles x 2048 floats = 64KB <= 80KB
        if (p == 1) {
            float* tb = xbuf + t*2048;
            #pragma unroll
            for (int mi = 0; mi < 2; mi++)
                #pragma unroll
                for (int nf = 0; nf < 8; nf++)
                    #pragma unroll
                    for (int q = 0; q < 4; q++) {
                        int row = mi*16 + (lane >> 2) + (q >> 1)*8;
                        int col = nf*8 + (lane & 3)*2 + (q & 1);
                        tb[row*64 + col] = acc[mi][nf][q];
                    }
        }
        __syncthreads();
        if (p == 0) {
            const float* tb = xbuf + t*2048;
            #pragma unroll
            for (int mi = 0; mi < 2; mi++)
                #pragma unroll
                for (int nf = 0; nf < 8; nf++)
                    #pragma unroll
                    for (int q = 0; q < 4; q++) {
                        int rloc = mi*16 + (lane >> 2) + (q >> 1)*8;
                        int cloc = nf*8 + (lane & 3)*2 + (q & 1);
                        int col = bn + wn*64 + cloc;
                        if (col < JJ) {
                            float p0 = acc[mi][nf][q];
                            float p1 = tb[rloc*64 + cloc];
                            out[(size_t)(bm + wm*32 + rloc)*JJ + col] =
                                p0 + (p1 - p0) * 0.015625f;
                        }
                    }
        }
        __syncthreads();   // protect smem before next tile's loads
    }
}

// ---------------------------------------------------------------------------
// image_logits[b, j] = max_p logits[b, p, j]
// ---------------------------------------------------------------------------
__global__ void imgmax_kernel(const float* __restrict__ logits, float* __restrict__ img) {
    int t = blockIdx.x * blockDim.x + threadIdx.x;
    if (t >= BB*JJ) return;
    int b = t / JJ, j = t % JJ;
    const float* p = logits + (size_t)b*PP*JJ + j;
    float m = -1e30f;
    for (int i = 0; i < PP; i++) m = fmaxf(m, p[(size_t)i*JJ]);
    img[(size_t)b*JJ + j] = m;
}

// ---------------------------------------------------------------------------
// class_logits[b, c] = sum_k img[b, c, k]*sw[c, k] / TEMP
// ---------------------------------------------------------------------------
__global__ void cls_kernel(const float* __restrict__ img, float* __restrict__ cls) {
    int t = blockIdx.x * blockDim.x + threadIdx.x;
    if (t >= BB*NCLS) return;
    int b = t / NCLS, c = t % NCLS;
    float s = 0.0f;
    #pragma unroll
    for (int k = 0; k < KP; k++) s += img[(size_t)b*JJ + c*KP + k] * g_sw[c*KP+k];
    cls[t] = s / 0.2f;
}

// ---------------------------------------------------------------------------
// Per-class: deterministic compaction + Sinkhorn + assignment + P_new
// ---------------------------------------------------------------------------
#define MAXN 1024
__global__ __launch_bounds__(256) void sinkhorn_kernel(
        const float* __restrict__ logits, const int* __restrict__ labels,
        const float* __restrict__ proto, const float* __restrict__ rpt,
        float* __restrict__ assign, float* __restrict__ pnew) {
    const int c = blockIdx.x;
    const int tid = threadIdx.x;
    const int lane = tid & 31, w = tid >> 5;

    __shared__ int   s_idx[MAXN];
    __shared__ float Q[KP][MAXN];
    __shared__ float red[256];
    __shared__ int   warp_cnt[8], warp_off[8];
    __shared__ int   s_n;

    if (tid == 0) s_n = 0;
    __syncthreads();

    for (int base = 0; base < NN; base += 256) {
        int n = base + tid;
        bool p = (labels[n] == c);
        unsigned bal = __ballot_sync(0xffffffffu, p);
        if (lane == 0) warp_cnt[w] = __popc(bal);
        __syncthreads();
        if (tid == 0) {
            int s = s_n;
            #pragma unroll
            for (int i = 0; i < 8; i++) { warp_off[i] = s; s += warp_cnt[i]; }
            s_n = s;
        }
        __syncthreads();
        if (p) {
            int pos = warp_off[w] + __popc(bal & ((1u << lane) - 1u));
            if (pos < MAXN) s_idx[pos] = n;
        }
        __syncthreads();
    }
    const int Nc = min(s_n, MAXN);

    if (Nc == 0) {
        for (int x = tid; x < KP*DD; x += 256)
            pnew[(size_t)c*KP*DD + x] = proto[(size_t)c*KP*DD + x];
        return;
    }

    for (int i = tid; i < Nc; i += 256) {
        const float* lp = logits + (size_t)s_idx[i]*JJ + c*KP;
        #pragma unroll
        for (int k = 0; k < KP; k++) Q[k][i] = expf(lp[k] * 20.0f);
    }
    __syncthreads();

    float s = 0.0f;
    for (int k = 0; k < KP; k++)
        for (int i = tid; i < Nc; i += 256) s += Q[k][i];
    red[tid] = s; __syncthreads();
    for (int o = 128; o > 0; o >>= 1) { if (tid < o) red[tid] += red[tid+o]; __syncthreads(); }
    float tot = red[0];
    __syncthreads();
    float dTot = (tot > 0.0f) ? tot : 1.0f;
    for (int k = 0; k < KP; k++)
        for (int i = tid; i < Nc; i += 256) Q[k][i] /= dTot;
    __syncthreads();

    const float fNc = (float)Nc;
    for (int it = 0; it < 3; it++) {
        for (int k = 0; k < KP; k++) {
            float rs = 0.0f;
            for (int i = tid; i < Nc; i += 256) rs += Q[k][i];
            red[tid] = rs; __syncthreads();
            for (int o = 128; o > 0; o >>= 1) { if (tid < o) red[tid] += red[tid+o]; __syncthreads(); }
            float r = red[0];
            __syncthreads();
            float dr = (r > 0.0f) ? r : 1.0f;
            for (int i = tid; i < Nc; i += 256) Q[k][i] = Q[k][i] / dr / 5.0f;
            __syncthreads();
        }
        for (int i = tid; i < Nc; i += 256) {
            float cs = Q[0][i]+Q[1][i]+Q[2][i]+Q[3][i]+Q[4][i];
            float dc = (cs > 0.0f) ? cs : 1.0f;
            #pragma unroll
            for (int k = 0; k < KP; k++) Q[k][i] = Q[k][i] / dc / fNc;
        }
        __syncthreads();
    }
    for (int k = 0; k < KP; k++)
        for (int i = tid; i < Nc; i += 256) Q[k][i] *= fNc;
    __syncthreads();

    for (int i = tid; i < Nc; i += 256) {
        float best = Q[0][i]; int ba = 0;
        #pragma unroll
        for (int k = 1; k < KP; k++) if (Q[k][i] > best) { best = Q[k][i]; ba = k; }
        assign[s_idx[i]] = (float)(c*KP + ba);
    }
    __syncthreads();

    for (int i = tid; i < Nc; i += 256) {
        float inv = g_inv[s_idx[i]];
        #pragma unroll
        for (int k = 0; k < KP; k++) Q[k][i] *= inv;
    }
    __syncthreads();

    const int d0 = tid * 3;
    float acc[KP][3];
    #pragma unroll
    for (int k = 0; k < KP; k++) { acc[k][0]=0.f; acc[k][1]=0.f; acc[k][2]=0.f; }
    for (int i = 0; i < Nc; i++) {
        const float* xp = rpt + (size_t)s_idx[i]*DD + d0;
        float x0 = xp[0], x1 = xp[1], x2 = xp[2];
        #pragma unroll
        for (int k = 0; k < KP; k++) {
            float q = Q[k][i];
            acc[k][0] = fmaf(q, x0, acc[k][0]);
            acc[k][1] = fmaf(q, x1, acc[k][1]);
            acc[k][2] = fmaf(q, x2, acc[k][2]);
        }
    }
    const float g = 0.999f, og = 1.0f - 0.999f;
    #pragma unroll
    for (int k = 0; k < KP; k++) {
        size_t basep = ((size_t)c*KP + k)*DD + d0;
        #pragma unroll
        for (int j = 0; j < 3; j++)
            pnew[basep + j] = g * proto[basep + j] + og * acc[k][j];
    }
}

// ---------------------------------------------------------------------------
extern "C" void kernel_launch(void* const* d_in, const int* in_sizes, int n_in,
                              void* d_out, int out_size) {
    const float* pt    = (const float*)d_in[0];
    const float* rpt   = (const float*)d_in[1];
    const float* proto = (const float*)d_in[2];
    const float* sa    = (const float*)d_in[3];
    const int*   lbl   = (const int*)  d_in[4];
    float* out = (float*)d_out;

    cudaFuncSetAttribute(gemm_mma_kernel,
                         cudaFuncAttributeMaxDynamicSharedMemorySize, SMEM_GEMM);

    norm_kernel<<<(2*NN + JPAD + 7)/8, 256>>>(pt, rpt, proto);
    sw_kernel<<<1, 256>>>(sa);
    gemm_mma_kernel<<<148, 512, SMEM_GEMM>>>(out + OFF_LOGITS);
    imgmax_kernel<<<(BB*JJ + 255)/256, 256>>>(out + OFF_LOGITS, out + OFF_IMG);
    cls_kernel<<<(BB*NCLS + 255)/256, 256>>>(out + OFF_IMG, out + OFF_CLS);
    sinkhorn_kernel<<<CC, 256>>>(out + OFF_LOGITS, lbl, proto, rpt,
                                 out + OFF_ASGN, out + OFF_PNEW);
}